// round 2
// baseline (speedup 1.0000x reference)
#include <cuda_runtime.h>

// ---------------- problem constants ----------------
#define BATCH 16
#define L2TAPS 225          // 15*15
#define FCDIM  2048
#define HIN 128
#define WIN 128
#define HU 256
#define WU 256
#define OC1 64              // channels after dynamic conv
#define W1OUT (OC1*81)      // 5184 per batch

// ---------------- device scratch (no allocs allowed) ----------------
__device__ float g_kfc[BATCH*FCDIM];                         // 128 KB
__device__ float g_w1 [BATCH*W1OUT];                         // 324 KB
__device__ float g_up [BATCH*HU*WU];                         // 4 MB
__device__ float g_f1 [(size_t)BATCH*OC1*HU*WU];             // 256 MB
__device__ float g_f2 [(size_t)BATCH*OC1*HU*WU];             // 256 MB
__device__ float g_w2p[64*64*9];                             // repacked [ic][oc][9]

// ---------------- kernel 1: kfc = relu(kflat @ kl_w^T + kl_b) ----------------
__global__ void k_kfc(const float* __restrict__ kern,
                      const float* __restrict__ kl_w,
                      const float* __restrict__ kl_b) {
    __shared__ float sk[L2TAPS];
    int b = blockIdx.x;
    for (int i = threadIdx.x; i < L2TAPS; i += blockDim.x)
        sk[i] = kern[b*L2TAPS + i];
    __syncthreads();
    for (int j = threadIdx.x; j < FCDIM; j += blockDim.x) {
        float acc = kl_b[j];
        const float* w = kl_w + (size_t)j*L2TAPS;
        #pragma unroll 5
        for (int i = 0; i < L2TAPS; i++) acc = fmaf(sk[i], w[i], acc);
        g_kfc[b*FCDIM + j] = fmaxf(acc, 0.0f);
    }
}

// ---------------- kernel 2: w1 = kfc @ w1_w^T + w1_b ----------------
// grid 81 blocks, each computes 64 outputs x all 16 batches
__global__ void k_w1(const float* __restrict__ w1w,
                     const float* __restrict__ w1b) {
    __shared__ float sx[32*17];   // [k][b] padded
    __shared__ float sw[32*65];   // [k][o] padded
    int o0 = blockIdx.x * 64;
    int o  = threadIdx.x & 63;
    int bq = threadIdx.x >> 6;    // 0..3 -> b = bq + 4*i
    float acc[4] = {0.f, 0.f, 0.f, 0.f};
    for (int k0 = 0; k0 < FCDIM; k0 += 32) {
        for (int idx = threadIdx.x; idx < 64*32; idx += 256) {
            int ro = idx >> 5, ck = idx & 31;
            sw[ck*65 + ro] = w1w[(size_t)(o0 + ro)*FCDIM + k0 + ck];
        }
        for (int idx = threadIdx.x; idx < 16*32; idx += 256) {
            int rb = idx >> 5, ck = idx & 31;
            sx[ck*17 + rb] = g_kfc[rb*FCDIM + k0 + ck];
        }
        __syncthreads();
        #pragma unroll
        for (int k = 0; k < 32; k++) {
            float wv = sw[k*65 + o];
            acc[0] = fmaf(wv, sx[k*17 + bq     ], acc[0]);
            acc[1] = fmaf(wv, sx[k*17 + bq +  4], acc[1]);
            acc[2] = fmaf(wv, sx[k*17 + bq +  8], acc[2]);
            acc[3] = fmaf(wv, sx[k*17 + bq + 12], acc[3]);
        }
        __syncthreads();
    }
    float bias = w1b[o0 + o];
    #pragma unroll
    for (int i = 0; i < 4; i++)
        g_w1[(bq + 4*i)*W1OUT + o0 + o] = acc[i] + bias;
}

// ---------------- kernel 3: bilinear x2 upsample (half-pixel, edge clamp) ----
__global__ void k_up(const float* __restrict__ img) {
    int idx = blockIdx.x*blockDim.x + threadIdx.x;
    if (idx >= BATCH*HU*WU) return;
    int x = idx & 255, y = (idx >> 8) & 255, b = idx >> 16;
    float syf = y*0.5f - 0.25f;
    float sxf = x*0.5f - 0.25f;
    int y0 = (int)floorf(syf); float wy = syf - (float)y0;
    int x0 = (int)floorf(sxf); float wx = sxf - (float)x0;
    int y0c = max(y0, 0), y1c = min(y0+1, HIN-1);
    int x0c = max(x0, 0), x1c = min(x0+1, WIN-1);
    const float* p = img + (size_t)b*HIN*WIN;
    float v00 = p[y0c*WIN + x0c], v01 = p[y0c*WIN + x1c];
    float v10 = p[y1c*WIN + x0c], v11 = p[y1c*WIN + x1c];
    g_up[idx] = (1.f-wy)*((1.f-wx)*v00 + wx*v01) + wy*((1.f-wx)*v10 + wx*v11);
}

// ---------------- kernel 4: repack c2_w [oc][ic][9] -> [ic][oc][9] -----------
__global__ void k_pack(const float* __restrict__ c2w) {
    int idx = blockIdx.x*blockDim.x + threadIdx.x;
    if (idx >= 64*64*9) return;
    int k  = idx % 9;
    int ic = (idx / 9) % 64;
    int oc = idx / 576;
    g_w2p[ic*576 + oc*9 + k] = c2w[idx];
}

// ---------------- kernel 5: per-sample dynamic conv 9x9, 1->64, relu --------
// grid (8, 8, 16b*8ocg). block 256 = 16x16 threads, each 2x2 px, 8 oc.
// tile 32x32 px. halo buffer 40x40.
__global__ __launch_bounds__(256, 2)
void k_conv1() {
    __shared__ float sx[40*40];
    __shared__ float sw[8*81];
    int b   = blockIdx.z >> 3;
    int ocg = blockIdx.z & 7;
    int gx0 = blockIdx.x*32 - 4;
    int gy0 = blockIdx.y*32 - 4;
    int tx = threadIdx.x & 15, ty = threadIdx.x >> 4;   // 16x16 threads

    const float* src = g_up + (size_t)b*HU*WU;
    for (int idx = threadIdx.x; idx < 40*40; idx += 256) {
        int r = idx / 40, c = idx - r*40;
        int gy = gy0 + r, gx = gx0 + c;
        sx[idx] = (gy >= 0 && gy < HU && gx >= 0 && gx < WU)
                  ? src[gy*WU + gx] : 0.f;
    }
    const float* wsrc = g_w1 + b*W1OUT + ocg*8*81;
    for (int idx = threadIdx.x; idx < 8*81; idx += 256) sw[idx] = wsrc[idx];
    __syncthreads();

    float acc[8][4];
    #pragma unroll
    for (int o = 0; o < 8; o++)
        #pragma unroll
        for (int i = 0; i < 4; i++) acc[o][i] = 0.f;

    int bx = 2*tx, by = 2*ty;                  // 0..30 in a 32x32 tile
    for (int dy = 0; dy < 9; dy++) {
        #pragma unroll
        for (int dx = 0; dx < 9; dx++) {
            float xv0 = sx[(by+dy)*40 + bx+dx];
            float xv1 = sx[(by+dy)*40 + bx+dx+1];
            float xv2 = sx[(by+dy+1)*40 + bx+dx];
            float xv3 = sx[(by+dy+1)*40 + bx+dx+1];
            #pragma unroll
            for (int o = 0; o < 8; o++) {
                float wv = sw[o*81 + dy*9 + dx];
                acc[o][0] = fmaf(wv, xv0, acc[o][0]);
                acc[o][1] = fmaf(wv, xv1, acc[o][1]);
                acc[o][2] = fmaf(wv, xv2, acc[o][2]);
                acc[o][3] = fmaf(wv, xv3, acc[o][3]);
            }
        }
    }

    #pragma unroll
    for (int o = 0; o < 8; o++) {
        int oc = ocg*8 + o;
        float* dst = g_f1 + ((size_t)(b*OC1 + oc))*HU*WU;
        int y = blockIdx.y*32 + by;
        int x = blockIdx.x*32 + bx;
        dst[y*WU + x]         = fmaxf(acc[o][0], 0.f);
        dst[y*WU + x + 1]     = fmaxf(acc[o][1], 0.f);
        dst[(y+1)*WU + x]     = fmaxf(acc[o][2], 0.f);
        dst[(y+1)*WU + x + 1] = fmaxf(acc[o][3], 0.f);
    }
}

// ---------------- kernel 6: conv 3x3, 64->64, +bias, relu (the big one) -----
// grid (16,16,16b). block 256. tile 16x16 px, all 64 oc.
// thread: oc group g = tid>>5 (8 oc), lane -> (r0 = lane>>4, c = lane&15),
// 8 px rows r0, r0+2, ..., r0+14. 64 fp32 accumulators.
__global__ __launch_bounds__(256, 2)
void k_conv2(const float* __restrict__ c2b) {
    __shared__ float sx[18*18];
    __shared__ float sw[576];
    int b  = blockIdx.z;
    int x0 = blockIdx.x*16 - 1;
    int y0 = blockIdx.y*16 - 1;
    int g    = threadIdx.x >> 5;
    int lane = threadIdx.x & 31;
    int c  = lane & 15;
    int r0 = lane >> 4;

    float acc[8][8];
    #pragma unroll
    for (int o = 0; o < 8; o++)
        #pragma unroll
        for (int j = 0; j < 8; j++) acc[o][j] = 0.f;

    const float* f1b = g_f1 + (size_t)b*OC1*HU*WU;

    for (int ic = 0; ic < 64; ic++) {
        __syncthreads();
        const float* src = f1b + (size_t)ic*HU*WU;
        for (int idx = threadIdx.x; idx < 324; idx += 256) {
            int rr = idx / 18, cc = idx - rr*18;
            int gy = y0 + rr, gx = x0 + cc;
            sx[idx] = (gy >= 0 && gy < HU && gx >= 0 && gx < WU)
                      ? src[gy*WU + gx] : 0.f;
        }
        const float* wsrc = g_w2p + ic*576;
        for (int idx = threadIdx.x; idx < 576; idx += 256) sw[idx] = wsrc[idx];
        __syncthreads();

        #pragma unroll
        for (int dy = 0; dy < 3; dy++) {
            #pragma unroll
            for (int dx = 0; dx < 3; dx++) {
                float wv[8];
                #pragma unroll
                for (int o = 0; o < 8; o++)
                    wv[o] = sw[(g*8 + o)*9 + dy*3 + dx];
                #pragma unroll
                for (int j = 0; j < 8; j++) {
                    float xv = sx[(r0 + 2*j + dy)*18 + c + dx];
                    #pragma unroll
                    for (int o = 0; o < 8; o++)
                        acc[o][j] = fmaf(wv[o], xv, acc[o][j]);
                }
            }
        }
    }

    #pragma unroll
    for (int o = 0; o < 8; o++) {
        int oc = g*8 + o;
        float bias = c2b[oc];
        float* dst = g_f2 + ((size_t)(b*OC1 + oc))*HU*WU;
        #pragma unroll
        for (int j = 0; j < 8; j++) {
            int y = blockIdx.y*16 + r0 + 2*j;
            int x = blockIdx.x*16 + c;
            dst[y*WU + x] = fmaxf(acc[o][j] + bias, 0.f);
        }
    }
}

// ---------------- kernel 7: conv 5x5, 64->1, +bias ----------------
// grid (8,8,16). block 256 = 32x8 threads, each 4 rows -> 32x32 tile.
__global__ __launch_bounds__(256, 2)
void k_conv3(const float* __restrict__ c3w,
             const float* __restrict__ c3b,
             float* __restrict__ out) {
    __shared__ float sw[1600];
    __shared__ float sx[36*36];
    int b  = blockIdx.z;
    int x0 = blockIdx.x*32 - 2;
    int y0 = blockIdx.y*32 - 2;
    int tx = threadIdx.x & 31, ty = threadIdx.x >> 5;

    for (int idx = threadIdx.x; idx < 1600; idx += 256) sw[idx] = c3w[idx];

    float acc[4] = {0.f, 0.f, 0.f, 0.f};
    const float* f2b = g_f2 + (size_t)b*OC1*HU*WU;

    for (int ic = 0; ic < 64; ic++) {
        __syncthreads();
        const float* src = f2b + (size_t)ic*HU*WU;
        for (int idx = threadIdx.x; idx < 36*36; idx += 256) {
            int rr = idx / 36, cc = idx - rr*36;
            int gy = y0 + rr, gx = x0 + cc;
            sx[idx] = (gy >= 0 && gy < HU && gx >= 0 && gx < WU)
                      ? src[gy*WU + gx] : 0.f;
        }
        __syncthreads();

        #pragma unroll
        for (int dy = 0; dy < 5; dy++) {
            #pragma unroll
            for (int dx = 0; dx < 5; dx++) {
                float wv = sw[ic*25 + dy*5 + dx];
                #pragma unroll
                for (int k = 0; k < 4; k++)
                    acc[k] = fmaf(wv, sx[(ty*4 + k + dy)*36 + tx + dx], acc[k]);
            }
        }
    }

    float bias = c3b[0];
    #pragma unroll
    for (int k = 0; k < 4; k++) {
        int y = blockIdx.y*32 + ty*4 + k;
        int x = blockIdx.x*32 + tx;
        out[(size_t)b*HU*WU + y*WU + x] = acc[k] + bias;
    }
}

// ---------------- launch ----------------
extern "C" void kernel_launch(void* const* d_in, const int* in_sizes, int n_in,
                              void* d_out, int out_size) {
    (void)in_sizes; (void)n_in; (void)out_size;
    const float* img  = (const float*)d_in[0];
    const float* kern = (const float*)d_in[1];
    const float* kl_w = (const float*)d_in[2];
    const float* kl_b = (const float*)d_in[3];
    const float* w1_w = (const float*)d_in[4];
    const float* w1_b = (const float*)d_in[5];
    const float* c2_w = (const float*)d_in[6];
    const float* c2_b = (const float*)d_in[7];
    const float* c3_w = (const float*)d_in[8];
    const float* c3_b = (const float*)d_in[9];
    float* out = (float*)d_out;

    k_kfc <<<BATCH, 256>>>(kern, kl_w, kl_b);
    k_w1  <<<W1OUT/64, 256>>>(w1_w, w1_b);
    k_up  <<<(BATCH*HU*WU)/256, 256>>>(img);
    k_pack<<<(64*64*9 + 255)/256, 256>>>(c2_w);
    k_conv1<<<dim3(8, 8, BATCH*8), 256>>>();
    k_conv2<<<dim3(16, 16, BATCH), 256>>>(c2_b);
    k_conv3<<<dim3(8, 8, BATCH), 256>>>(c3_w, c3_b, out);
}